// round 11
// baseline (speedup 1.0000x reference)
#include <cuda_runtime.h>

#define NQ 4
#define NL 8

__device__ __forceinline__ float fneg_alu(float v) {
    return __uint_as_float(__float_as_uint(v) ^ 0x80000000u);
}
__device__ __forceinline__ float2 cmulf(float2 a, float2 b) {
    return make_float2(a.x * b.x - a.y * b.y, a.x * b.y + a.y * b.x);
}

// Fused SU(2) gate G = [[g00, -conj(g10)],[g10, conj(g00)]] on qubit with
// amplitude stride K (compile-time). Scalar FFMA, negations folded into sources.
// Row i: new_a = g00*a - conj(g10)*b
//   real: g00r*ar - g00i*ai - g10r*br - g10i*bi
//   imag: g00r*ai + g00i*ar - g10r*bi + g10i*br
// Row j: new_b = g10*a + conj(g00)*b
//   real: g10r*ar - g10i*ai + g00r*br + g00i*bi
//   imag: g10r*ai + g10i*ar + g00r*bi - g00i*br
// (verified against the validated packed-R5 coefficient sets)
template <int K>
__device__ __forceinline__ void apply_g(float sr[16], float si[16],
                                        float g00r, float g00i, float g10r, float g10i) {
#pragma unroll
    for (int mm = 0; mm < 8; mm++) {
        int i = ((mm & ~(K - 1)) << 1) | (mm & (K - 1));
        int j = i | K;
        float ar = sr[i], ai = si[i], br = sr[j], bi = si[j];
        sr[i] = g00r * ar - g00i * ai - g10r * br - g10i * bi;
        si[i] = g00r * ai + g00i * ar - g10r * bi + g10i * br;
        sr[j] = g10r * ar - g10i * ai + g00r * br + g00i * bi;
        si[j] = g10r * ai + g10i * ar + g00r * bi - g00i * br;
    }
}

__global__ void __launch_bounds__(256)
pqc_kernel(const float* __restrict__ x, const float* __restrict__ theta,
           const float* __restrict__ lmbd, float* __restrict__ out, int B) {
    // 36 gates, SU(2): store only {u00r, u00i, u10r, u10i} per gate.
    __shared__ float4 sU4[36];
    __shared__ float sl[32];

    int t = threadIdx.x;
    if (t < 32) sl[t] = lmbd[t];

    if (t < 36) {
        int g = t;
        float t0 = theta[g * 3 + 0], t1 = theta[g * 3 + 1], t2 = theta[g * 3 + 2];
        float cx, sx, cy, sy, cz, sz;
        sincosf(0.5f * t0, &sx, &cx);
        sincosf(0.5f * t1, &sy, &cy);
        sincosf(0.5f * t2, &sz, &cz);
        // M = RY*RX (column 0 entries)
        float m00r = cy * cx, m00i = sy * sx;
        float m10r = sy * cx, m10i = -cy * sx;
        // U = RZ*M: u00 = (cz - i sz)*m00 ; u10 = (cz + i sz)*m10
        float u00r = cz * m00r + sz * m00i, u00i = cz * m00i - sz * m00r;
        float u10r = cz * m10r - sz * m10i, u10i = cz * m10i + sz * m10r;
        sU4[g] = make_float4(u00r, u00i, u10r, u10i);
    }
    __syncthreads();

    int b = blockIdx.x * blockDim.x + t;
    if (b >= B) return;

    float4 xv = reinterpret_cast<const float4*>(x)[b];
    float xa[4] = {xv.x, xv.y, xv.z, xv.w};

    // ---- init: layer-0 gates on |0000> = outer product of column-0 entries ----
    // amplitude index i: qubit q -> bit (3-q).
    float sr[16], si[16];
    {
        float4 g0 = sU4[0], g1 = sU4[1], g2 = sU4[2], g3 = sU4[3];
        float2 c0[2] = {{g0.x, g0.y}, {g0.z, g0.w}};
        float2 c1[2] = {{g1.x, g1.y}, {g1.z, g1.w}};
        float2 c2[2] = {{g2.x, g2.y}, {g2.z, g2.w}};
        float2 c3[2] = {{g3.x, g3.y}, {g3.z, g3.w}};
        float2 t01[4], t23[4];
#pragma unroll
        for (int j = 0; j < 4; j++) {
            t01[j] = cmulf(c0[j >> 1], c1[j & 1]);
            t23[j] = cmulf(c2[j >> 1], c3[j & 1]);
        }
#pragma unroll
        for (int i = 0; i < 16; i++) {
            float2 v = cmulf(t01[i >> 2], t23[i & 3]);
            sr[i] = v.x;
            si[i] = v.y;
        }
    }

#pragma unroll 1
    for (int l = 0; l < NL; l++) {
        // CZ ring: negate amplitudes 3, 6, 9, 12 (ALU XOR, off the fma pipe)
        sr[3] = fneg_alu(sr[3]);   si[3] = fneg_alu(si[3]);
        sr[6] = fneg_alu(sr[6]);   si[6] = fneg_alu(si[6]);
        sr[9] = fneg_alu(sr[9]);   si[9] = fneg_alu(si[9]);
        sr[12] = fneg_alu(sr[12]); si[12] = fneg_alu(si[12]);

        // Fused gates G_q = U_{l+1,q} * RX(lmbd*x) per qubit (distinct-qubit factors commute)
#pragma unroll
        for (int q = 0; q < 4; q++) {
            float4 u = sU4[(l + 1) * 4 + q];   // {u00r, u00i, u10r, u10i}
            float ang = 0.5f * sl[l * 4 + q] * xa[q];
            float s, c;
            __sincosf(ang, &s, &c);
            // G = U * RX(c, s): (u01 = -conj(u10), u11 = conj(u00))
            float g00r = u.x * c + u.w * s;    // u00r*c + u10i*s
            float g00i = u.y * c + u.z * s;    // u00i*c + u10r*s
            float g10r = u.z * c - u.y * s;    // u10r*c - u00i*s
            float g10i = u.w * c - u.x * s;    // u10i*c - u00r*s
            if (q == 0)      apply_g<8>(sr, si, g00r, g00i, g10r, g10i);
            else if (q == 1) apply_g<4>(sr, si, g00r, g00i, g10r, g10i);
            else if (q == 2) apply_g<2>(sr, si, g00r, g00i, g10r, g10i);
            else             apply_g<1>(sr, si, g00r, g00i, g10r, g10i);
        }
    }

    // <Z0 Z1 Z2 Z3>: sign = (-1)^popc(i)
    float ep = 0.0f, en = 0.0f;
#pragma unroll
    for (int i = 0; i < 16; i++) {
        float p = sr[i] * sr[i] + si[i] * si[i];
        if (__popc(i) & 1) en += p; else ep += p;
    }
    out[b] = ep - en;
}

extern "C" void kernel_launch(void* const* d_in, const int* in_sizes, int n_in,
                              void* d_out, int out_size) {
    const float* x     = (const float*)d_in[0];   // [B, 4]
    const float* theta = (const float*)d_in[1];   // [1, 108]
    const float* lmbd  = (const float*)d_in[2];   // [32]
    float* out = (float*)d_out;                   // [B, 1]
    int B = in_sizes[0] / NQ;

    const int threads = 256;
    int blocks = (B + threads - 1) / threads;     // 1024 for B=262144
    pqc_kernel<<<blocks, threads>>>(x, theta, lmbd, out, B);
}

// round 14
// speedup vs baseline: 1.0294x; 1.0294x over previous
#include <cuda_runtime.h>

#define NQ 4
#define NL 8

__device__ __forceinline__ float2 cmulf(float2 a, float2 b) {
    return make_float2(a.x * b.x - a.y * b.y, a.x * b.y + a.y * b.x);
}

// Fused SU(2) gate G = [[g00, -conj(g10)],[g10, conj(g00)]] on qubit with
// amplitude stride K (compile-time). Scalar FFMA, negations folded into sources.
// (sign set validated in R11: rel_err 3.6e-6)
template <int K>
__device__ __forceinline__ void apply_g(float sr[16], float si[16],
                                        float g00r, float g00i, float g10r, float g10i) {
#pragma unroll
    for (int mm = 0; mm < 8; mm++) {
        int i = ((mm & ~(K - 1)) << 1) | (mm & (K - 1));
        int j = i | K;
        float ar = sr[i], ai = si[i], br = sr[j], bi = si[j];
        sr[i] = g00r * ar - g00i * ai - g10r * br - g10i * bi;
        si[i] = g00r * ai + g00i * ar - g10r * bi + g10i * br;
        sr[j] = g10r * ar - g10i * ai + g00r * br + g00i * bi;
        si[j] = g10r * ai + g10i * ar + g00r * bi - g00i * br;
    }
}

__device__ __forceinline__ void neg_cz(float sr[16], float si[16]) {
    sr[3] = -sr[3];   si[3] = -si[3];
    sr[6] = -sr[6];   si[6] = -si[6];
    sr[9] = -sr[9];   si[9] = -si[9];
    sr[12] = -sr[12]; si[12] = -si[12];
}

__device__ __forceinline__ float expval_z4(const float sr[16], const float si[16]) {
    float ep = 0.0f, en = 0.0f;
#pragma unroll
    for (int i = 0; i < 16; i++) {
        float p = sr[i] * sr[i] + si[i] * si[i];
        if (__popc(i) & 1) en += p; else ep += p;
    }
    return ep - en;
}

__global__ void __launch_bounds__(128)
pqc_kernel(const float* __restrict__ x, const float* __restrict__ theta,
           const float* __restrict__ lmbd, float* __restrict__ out, int B) {
    // 36 gates, SU(2): store only {u00r, u00i, u10r, u10i} per gate.
    __shared__ float4 sU4[36];
    __shared__ float sl[32];

    int t = threadIdx.x;
    if (t < 32) sl[t] = lmbd[t];

    if (t < 36) {
        int g = t;
        float t0 = theta[g * 3 + 0], t1 = theta[g * 3 + 1], t2 = theta[g * 3 + 2];
        float cx, sx, cy, sy, cz, sz;
        sincosf(0.5f * t0, &sx, &cx);
        sincosf(0.5f * t1, &sy, &cy);
        sincosf(0.5f * t2, &sz, &cz);
        // M = RY*RX (column 0 entries)
        float m00r = cy * cx, m00i = sy * sx;
        float m10r = sy * cx, m10i = -cy * sx;
        // U = RZ*M: u00 = (cz - i sz)*m00 ; u10 = (cz + i sz)*m10
        float u00r = cz * m00r + sz * m00i, u00i = cz * m00i - sz * m00r;
        float u10r = cz * m10r - sz * m10i, u10i = cz * m10i + sz * m10r;
        sU4[g] = make_float4(u00r, u00i, u10r, u10i);
    }
    __syncthreads();

    const int stride = gridDim.x * blockDim.x;
    int b0 = blockIdx.x * blockDim.x + t;
    int b1 = b0 + stride;
    if (b0 >= B) return;
    bool have1 = (b1 < B);

    float4 xv0 = reinterpret_cast<const float4*>(x)[b0];
    float4 xv1 = have1 ? reinterpret_cast<const float4*>(x)[b1] : xv0;
    float xa0[4] = {xv0.x, xv0.y, xv0.z, xv0.w};
    float xa1[4] = {xv1.x, xv1.y, xv1.z, xv1.w};

    // ---- init (theta-only, identical for both samples): layer-0 on |0000> ----
    float sr0[16], si0[16], sr1[16], si1[16];
    {
        float4 g0 = sU4[0], g1 = sU4[1], g2 = sU4[2], g3 = sU4[3];
        float2 c0[2] = {{g0.x, g0.y}, {g0.z, g0.w}};
        float2 c1[2] = {{g1.x, g1.y}, {g1.z, g1.w}};
        float2 c2[2] = {{g2.x, g2.y}, {g2.z, g2.w}};
        float2 c3[2] = {{g3.x, g3.y}, {g3.z, g3.w}};
        float2 t01[4], t23[4];
#pragma unroll
        for (int j = 0; j < 4; j++) {
            t01[j] = cmulf(c0[j >> 1], c1[j & 1]);
            t23[j] = cmulf(c2[j >> 1], c3[j & 1]);
        }
#pragma unroll
        for (int i = 0; i < 16; i++) {
            float2 v = cmulf(t01[i >> 2], t23[i & 3]);
            sr0[i] = v.x; si0[i] = v.y;
            sr1[i] = v.x; si1[i] = v.y;
        }
    }

#pragma unroll 1
    for (int l = 0; l < NL; l++) {
        // CZ ring: negate amplitudes 3, 6, 9, 12 (folds into FFMA source modifiers)
        neg_cz(sr0, si0);
        neg_cz(sr1, si1);

        // Fused gates G_q = U_{l+1,q} * RX(lmbd*x) per qubit, both samples interleaved
#pragma unroll
        for (int q = 0; q < 4; q++) {
            float4 u = sU4[(l + 1) * 4 + q];   // {u00r, u00i, u10r, u10i}
            float lm = 0.5f * sl[l * 4 + q];
            float s0, c0a, s1, c1a;
            __sincosf(lm * xa0[q], &s0, &c0a);
            __sincosf(lm * xa1[q], &s1, &c1a);
            // G = U * RX(c, s): (u01 = -conj(u10), u11 = conj(u00))
            float a00r = u.x * c0a + u.w * s0;
            float a00i = u.y * c0a + u.z * s0;
            float a10r = u.z * c0a - u.y * s0;
            float a10i = u.w * c0a - u.x * s0;
            float b00r = u.x * c1a + u.w * s1;
            float b00i = u.y * c1a + u.z * s1;
            float b10r = u.z * c1a - u.y * s1;
            float b10i = u.w * c1a - u.x * s1;
            if (q == 0) {
                apply_g<8>(sr0, si0, a00r, a00i, a10r, a10i);
                apply_g<8>(sr1, si1, b00r, b00i, b10r, b10i);
            } else if (q == 1) {
                apply_g<4>(sr0, si0, a00r, a00i, a10r, a10i);
                apply_g<4>(sr1, si1, b00r, b00i, b10r, b10i);
            } else if (q == 2) {
                apply_g<2>(sr0, si0, a00r, a00i, a10r, a10i);
                apply_g<2>(sr1, si1, b00r, b00i, b10r, b10i);
            } else {
                apply_g<1>(sr0, si0, a00r, a00i, a10r, a10i);
                apply_g<1>(sr1, si1, b00r, b00i, b10r, b10i);
            }
        }
    }

    out[b0] = expval_z4(sr0, si0);
    if (have1) out[b1] = expval_z4(sr1, si1);
}

extern "C" void kernel_launch(void* const* d_in, const int* in_sizes, int n_in,
                              void* d_out, int out_size) {
    const float* x     = (const float*)d_in[0];   // [B, 4]
    const float* theta = (const float*)d_in[1];   // [1, 108]
    const float* lmbd  = (const float*)d_in[2];   // [32]
    float* out = (float*)d_out;                   // [B, 1]
    int B = in_sizes[0] / NQ;

    const int threads = 128;
    const int spt = 2;  // samples per thread, interleaved in registers
    int blocks = (B + threads * spt - 1) / (threads * spt);   // 1024 for B=262144
    pqc_kernel<<<blocks, threads>>>(x, theta, lmbd, out, B);
}